// round 7
// baseline (speedup 1.0000x reference)
#include <cuda_runtime.h>
#include <cstdint>

// KVDequantizer: Q4 nibble unpack + per-block(32) scale/bias.
// Inputs (metadata order):
//   d_in[0] k_packed int32 [2, 131072, 16]
//   d_in[1] k_scale  f32   [2, 131072, 1]
//   d_in[2] k_bias   f32   [2, 131072, 1]
//   d_in[3] v_packed int32 [2, 131072, 16]
//   d_in[4] v_scale  f32   [2, 131072, 1]
//   d_in[5] v_bias   f32   [2, 131072, 1]
// Output: [k_flat (8388608 f32) | v_flat (8388608 f32)]
//
// Each thread processes TWO int4 (16 B packed each) from far-apart halves of
// its tensor -> 2 independent load streams (MLP=2) with fully coalesced
// lane-contiguous loads and stores. Plain (default-cached) loads/stores:
// R2 showed .cs hints regress.

static constexpr int N_INT4_PER_TENSOR = 2 * 131072 * 16 / 4;  // 1,048,576
static constexpr int HALF = N_INT4_PER_TENSOR / 2;             // 524,288

__device__ __forceinline__ void dequant8(int4 x, float sc, float bi,
                                         float4& r0, float4& r1)
{
    r0.x = (float)( x.x       & 15) * sc + bi;
    r0.y = (float)((x.x >> 4) & 15) * sc + bi;
    r0.z = (float)( x.y       & 15) * sc + bi;
    r0.w = (float)((x.y >> 4) & 15) * sc + bi;
    r1.x = (float)( x.z       & 15) * sc + bi;
    r1.y = (float)((x.z >> 4) & 15) * sc + bi;
    r1.z = (float)( x.w       & 15) * sc + bi;
    r1.w = (float)((x.w >> 4) & 15) * sc + bi;
}

__global__ __launch_bounds__(256) void kv_dequant_kernel(
    const int4* __restrict__ kp, const float* __restrict__ ks, const float* __restrict__ kb,
    const int4* __restrict__ vp, const float* __restrict__ vs, const float* __restrict__ vb,
    float4* __restrict__ out)
{
    int i = blockIdx.x * blockDim.x + threadIdx.x;

    const int4* p;
    const float* s;
    const float* b;
    float4* o;
    int j;

    if (i < HALF) {
        p = kp; s = ks; b = kb; o = out; j = i;
    } else {
        p = vp; s = vs; b = vb;
        o = out + 2 * N_INT4_PER_TENSOR;   // float4 offset of v region
        j = i - HALF;
    }

    int ja = j;              // stream A: first half of tensor
    int jb = j + HALF;       // stream B: second half of tensor

    // Issue both big loads + all scalar loads before any consumption.
    int4 xa = p[ja];
    int4 xb = p[jb];
    float sca = __ldg(s + (ja >> 2));
    float bia = __ldg(b + (ja >> 2));
    float scb = __ldg(s + (jb >> 2));
    float bib = __ldg(b + (jb >> 2));

    float4 a0, a1, b0, b1;
    dequant8(xa, sca, bia, a0, a1);
    dequant8(xb, scb, bib, b0, b1);

    o[2 * ja]     = a0;
    o[2 * ja + 1] = a1;
    o[2 * jb]     = b0;
    o[2 * jb + 1] = b1;
}

extern "C" void kernel_launch(void* const* d_in, const int* in_sizes, int n_in,
                              void* d_out, int out_size)
{
    const int4*  kp = (const int4*) d_in[0];
    const float* ks = (const float*)d_in[1];
    const float* kb = (const float*)d_in[2];
    const int4*  vp = (const int4*) d_in[3];
    const float* vs = (const float*)d_in[4];
    const float* vb = (const float*)d_in[5];
    float4* out = (float4*)d_out;

    const int total_threads = 2 * HALF;        // 1,048,576
    const int block = 256;
    const int grid = total_threads / block;    // 4096

    kv_dequant_kernel<<<grid, block>>>(kp, ks, kb, vp, vs, vb, out);
}

// round 10
// speedup vs baseline: 1.1943x; 1.1943x over previous
#include <cuda_runtime.h>
#include <cstdint>

// KVDequantizer: Q4 nibble unpack + per-block(32) scale/bias.
// Bulk-async (TMA 1D) pipelined version: persistent CTAs stage packed data +
// scale/bias into smem via cp.async.bulk (mbarrier complete_tx), dequantize
// smem->smem, and write out via cp.async.bulk bulk_group stores.
//
// Inputs (metadata order):
//   d_in[0] k_packed int32 [2, 131072, 16]   (each int32 holds one byte = 2 nibbles = 2 elems)
//   d_in[1] k_scale  f32   [2, 131072, 1]
//   d_in[2] k_bias   f32   [2, 131072, 1]
//   d_in[3] v_packed int32 [2, 131072, 16]
//   d_in[4] v_scale  f32   [2, 131072, 1]
//   d_in[5] v_bias   f32   [2, 131072, 1]
// Output: [k_flat (8388608 f32) | v_flat (8388608 f32)]

#define TILE_ELEMS      8192                       // output floats per tile
#define IN_PACKED_B     (TILE_ELEMS * 2)           // 16384 B (4 B per 2 elems)
#define SB_B            (TILE_ELEMS / 32 * 4)      // 1024 B (256 blocks * f32)
#define IN_STAGE_B      (IN_PACKED_B + 2 * SB_B)   // 18432
#define OUT_STAGE_B     (TILE_ELEMS * 4)           // 32768

#define SMEM_IN0        0
#define SMEM_IN1        IN_STAGE_B
#define SMEM_OUT0       (2 * IN_STAGE_B)
#define SMEM_OUT1       (2 * IN_STAGE_B + OUT_STAGE_B)
#define SMEM_MBAR       (2 * IN_STAGE_B + 2 * OUT_STAGE_B)   // 102400
#define SMEM_TOTAL      (SMEM_MBAR + 64)

#define TILES_PER_TENSOR 1024
#define TOTAL_TILES      2048
#define GRID             304        // 2 CTAs/SM * 152 SMs, persistent
#define NTHREADS         256

__device__ __forceinline__ uint32_t smem_u32(const void* p) {
    return (uint32_t)__cvta_generic_to_shared((void*)p);
}

__device__ __forceinline__ void mbar_init(uint32_t mbar, uint32_t count) {
    asm volatile("mbarrier.init.shared.b64 [%0], %1;" :: "r"(mbar), "r"(count) : "memory");
}

__device__ __forceinline__ void mbar_expect_tx(uint32_t mbar, uint32_t bytes) {
    asm volatile("mbarrier.arrive.expect_tx.shared.b64 _, [%0], %1;"
                 :: "r"(mbar), "r"(bytes) : "memory");
}

__device__ __forceinline__ void mbar_wait(uint32_t mbar, uint32_t parity) {
    uint32_t done;
    asm volatile(
        "{\n\t.reg .pred p;\n\t"
        "mbarrier.try_wait.parity.acquire.cta.shared::cta.b64 p, [%1], %2;\n\t"
        "selp.b32 %0, 1, 0, p;\n\t}"
        : "=r"(done) : "r"(mbar), "r"(parity) : "memory");
    if (!done) {
        asm volatile(
            "{\n\t.reg .pred P1;\n\t"
            "WL_%=:\n\t"
            "mbarrier.try_wait.parity.acquire.cta.shared::cta.b64 P1, [%0], %1, 0x989680;\n\t"
            "@P1 bra.uni WD_%=;\n\t"
            "bra.uni WL_%=;\n\t"
            "WD_%=:\n\t}"
            :: "r"(mbar), "r"(parity) : "memory");
    }
}

__device__ __forceinline__ void bulk_g2s(uint32_t smem_dst, const void* gmem_src,
                                         uint32_t bytes, uint32_t mbar) {
    asm volatile(
        "cp.async.bulk.shared::cta.global.mbarrier::complete_tx::bytes [%0], [%1], %2, [%3];"
        :: "r"(smem_dst), "l"(gmem_src), "r"(bytes), "r"(mbar) : "memory");
}

__device__ __forceinline__ void bulk_s2g(void* gmem_dst, uint32_t smem_src, uint32_t bytes) {
    asm volatile(
        "cp.async.bulk.global.shared::cta.bulk_group [%0], [%1], %2;"
        :: "l"(gmem_dst), "r"(smem_src), "r"(bytes) : "memory");
}

__global__ __launch_bounds__(NTHREADS, 2) void kv_dequant_tma(
    const char* __restrict__ kp, const char* __restrict__ ks, const char* __restrict__ kb,
    const char* __restrict__ vp, const char* __restrict__ vs, const char* __restrict__ vb,
    char* __restrict__ out)
{
    extern __shared__ char smem[];
    const uint32_t sbase = smem_u32(smem);
    const int tid = threadIdx.x;

    if (tid == 0) {
        mbar_init(sbase + SMEM_MBAR, 1);
        mbar_init(sbase + SMEM_MBAR + 16, 1);
    }
    __syncthreads();

    // Issue input loads for tile t into stage s (thread 0 only).
    auto issue_loads = [&](int t, int s) {
        int tensor = t >> 10;                // 0 = k, 1 = v
        int local  = t & (TILES_PER_TENSOR - 1);
        const char* p  = tensor ? vp : kp;
        const char* sc = tensor ? vs : ks;
        const char* bi = tensor ? vb : kb;
        uint32_t mb  = sbase + SMEM_MBAR + 16 * s;
        uint32_t dst = sbase + (s ? SMEM_IN1 : SMEM_IN0);
        mbar_expect_tx(mb, IN_STAGE_B);
        bulk_g2s(dst,                        p  + (size_t)local * IN_PACKED_B, IN_PACKED_B, mb);
        bulk_g2s(dst + IN_PACKED_B,          sc + (size_t)local * SB_B,        SB_B,        mb);
        bulk_g2s(dst + IN_PACKED_B + SB_B,   bi + (size_t)local * SB_B,        SB_B,        mb);
    };

    // Prologue: prefetch first tile into stage 0.
    if (tid == 0 && (int)blockIdx.x < TOTAL_TILES)
        issue_loads(blockIdx.x, 0);

    int ph0 = 0, ph1 = 0;
    int it = 0;
    for (int t = blockIdx.x; t < TOTAL_TILES; t += GRID, ++it) {
        const int s = it & 1;

        // Prefetch next tile into the other stage (safe: that buffer's previous
        // consumer finished at the __syncthreads ending iteration it-1).
        const int tn = t + GRID;
        if (tid == 0 && tn < TOTAL_TILES)
            issue_loads(tn, s ^ 1);

        // Wait for this tile's input.
        const uint32_t mb = sbase + SMEM_MBAR + 16 * s;
        if (s == 0) { mbar_wait(mb, ph0); ph0 ^= 1; }
        else        { mbar_wait(mb, ph1); ph1 ^= 1; }

        // Ensure the out buffer we're about to write (used by tile it-2) has
        // been fully read by its bulk store. Allow 1 group (tile it-1) in flight.
        if (tid == 0)
            asm volatile("cp.async.bulk.wait_group.read 1;" ::: "memory");
        __syncthreads();

        // Dequantize: smem in-stage -> smem out-stage.
        const char* in  = smem + (s ? SMEM_IN1 : SMEM_IN0);
        char*       ob  = smem + (s ? SMEM_OUT1 : SMEM_OUT0);
        const int2*  pin  = (const int2*)in;
        const float* psc  = (const float*)(in + IN_PACKED_B);
        const float* pbi  = (const float*)(in + IN_PACKED_B + SB_B);
        float4*      pout = (float4*)ob;

        #pragma unroll
        for (int r = 0; r < TILE_ELEMS / 4 / NTHREADS; ++r) {   // 8 iters
            int idx = r * NTHREADS + tid;                        // float4 index 0..2047
            int2  x  = pin[idx];
            int   b  = idx >> 3;                                 // 8 float4 per 32-elem block
            float sc = psc[b];
            float bi = pbi[b];
            float4 v;
            v.x = (float)( x.x       & 15) * sc + bi;
            v.y = (float)((x.x >> 4) & 15) * sc + bi;
            v.z = (float)( x.y       & 15) * sc + bi;
            v.w = (float)((x.y >> 4) & 15) * sc + bi;
            pout[idx] = v;
        }
        __syncthreads();

        // Bulk store the finished tile.
        if (tid == 0) {
            asm volatile("fence.proxy.async.shared::cta;" ::: "memory");
            int tensor = t >> 10;
            int local  = t & (TILES_PER_TENSOR - 1);
            char* gdst = out + (size_t)tensor * (TILES_PER_TENSOR * (size_t)OUT_STAGE_B)
                             + (size_t)local * OUT_STAGE_B;
            bulk_s2g(gdst, sbase + (s ? SMEM_OUT1 : SMEM_OUT0), OUT_STAGE_B);
            asm volatile("cp.async.bulk.commit_group;" ::: "memory");
        }
    }

    // Drain all outstanding bulk stores before exit.
    if (tid == 0)
        asm volatile("cp.async.bulk.wait_group.read 0;" ::: "memory");
}

extern "C" void kernel_launch(void* const* d_in, const int* in_sizes, int n_in,
                              void* d_out, int out_size)
{
    const char* kp = (const char*)d_in[0];
    const char* ks = (const char*)d_in[1];
    const char* kb = (const char*)d_in[2];
    const char* vp = (const char*)d_in[3];
    const char* vs = (const char*)d_in[4];
    const char* vb = (const char*)d_in[5];

    cudaFuncSetAttribute(kv_dequant_tma,
                         cudaFuncAttributeMaxDynamicSharedMemorySize, SMEM_TOTAL);

    kv_dequant_tma<<<GRID, NTHREADS, SMEM_TOTAL>>>(
        kp, ks, kb, vp, vs, vb, (char*)d_out);
}

// round 13
// speedup vs baseline: 1.3190x; 1.1045x over previous
#include <cuda_runtime.h>
#include <cstdint>

// KVDequantizer: Q4 nibble unpack + per-block(32) scale/bias.
// R5: TMA (cp.async.bulk) 4-deep input pipeline into smem, dequant in regs,
// direct coalesced STG.128 stores to gmem (no out-staging).
//
// Inputs (metadata order):
//   d_in[0] k_packed int32 [2, 131072, 16]
//   d_in[1] k_scale  f32   [2, 131072, 1]
//   d_in[2] k_bias   f32   [2, 131072, 1]
//   d_in[3] v_packed int32 [2, 131072, 16]
//   d_in[4] v_scale  f32   [2, 131072, 1]
//   d_in[5] v_bias   f32   [2, 131072, 1]
// Output: [k_flat (8388608 f32) | v_flat (8388608 f32)]

#define TILE_ELEMS      4096                        // output floats per tile
#define IN_PACKED_B     (TILE_ELEMS * 2)            // 8192 B
#define SB_B            (TILE_ELEMS / 32 * 4)       // 512 B
#define IN_STAGE_B      (IN_PACKED_B + 2 * SB_B)    // 9216 B
#define NSTAGES         4
#define SMEM_MBAR       (NSTAGES * IN_STAGE_B)      // 36864
#define SMEM_TOTAL      (SMEM_MBAR + NSTAGES * 16)

#define TILES_PER_TENSOR 2048
#define TOTAL_TILES      4096
#define CTAS_PER_SM      4
#define GRID             (152 * CTAS_PER_SM)        // 608, persistent
#define NTHREADS         256
#define OUT_TILE_B       (TILE_ELEMS * 4)           // 16384 B

__device__ __forceinline__ uint32_t smem_u32(const void* p) {
    return (uint32_t)__cvta_generic_to_shared((void*)p);
}

__device__ __forceinline__ void mbar_init(uint32_t mbar, uint32_t count) {
    asm volatile("mbarrier.init.shared.b64 [%0], %1;" :: "r"(mbar), "r"(count) : "memory");
}

__device__ __forceinline__ void mbar_expect_tx(uint32_t mbar, uint32_t bytes) {
    asm volatile("mbarrier.arrive.expect_tx.shared.b64 _, [%0], %1;"
                 :: "r"(mbar), "r"(bytes) : "memory");
}

__device__ __forceinline__ void mbar_wait(uint32_t mbar, uint32_t parity) {
    uint32_t done;
    asm volatile(
        "{\n\t.reg .pred p;\n\t"
        "mbarrier.try_wait.parity.acquire.cta.shared::cta.b64 p, [%1], %2;\n\t"
        "selp.b32 %0, 1, 0, p;\n\t}"
        : "=r"(done) : "r"(mbar), "r"(parity) : "memory");
    if (!done) {
        asm volatile(
            "{\n\t.reg .pred P1;\n\t"
            "WL_%=:\n\t"
            "mbarrier.try_wait.parity.acquire.cta.shared::cta.b64 P1, [%0], %1, 0x989680;\n\t"
            "@P1 bra.uni WD_%=;\n\t"
            "bra.uni WL_%=;\n\t"
            "WD_%=:\n\t}"
            :: "r"(mbar), "r"(parity) : "memory");
    }
}

__device__ __forceinline__ void bulk_g2s(uint32_t smem_dst, const void* gmem_src,
                                         uint32_t bytes, uint32_t mbar) {
    asm volatile(
        "cp.async.bulk.shared::cta.global.mbarrier::complete_tx::bytes [%0], [%1], %2, [%3];"
        :: "r"(smem_dst), "l"(gmem_src), "r"(bytes), "r"(mbar) : "memory");
}

__global__ __launch_bounds__(NTHREADS, CTAS_PER_SM) void kv_dequant_tma2(
    const char* __restrict__ kp, const char* __restrict__ ks, const char* __restrict__ kb,
    const char* __restrict__ vp, const char* __restrict__ vs, const char* __restrict__ vb,
    char* __restrict__ out)
{
    extern __shared__ char smem[];
    const uint32_t sbase = smem_u32(smem);
    const int tid = threadIdx.x;

    if (tid == 0) {
        #pragma unroll
        for (int s = 0; s < NSTAGES; ++s)
            mbar_init(sbase + SMEM_MBAR + 16 * s, 1);
    }
    __syncthreads();

    auto issue_loads = [&](int t, int s) {
        int tensor = t >> 11;                       // 0 = k, 1 = v
        int local  = t & (TILES_PER_TENSOR - 1);
        const char* p  = tensor ? vp : kp;
        const char* sc = tensor ? vs : ks;
        const char* bi = tensor ? vb : kb;
        uint32_t mb  = sbase + SMEM_MBAR + 16 * s;
        uint32_t dst = sbase + s * IN_STAGE_B;
        mbar_expect_tx(mb, IN_STAGE_B);
        bulk_g2s(dst,                      p  + (size_t)local * IN_PACKED_B, IN_PACKED_B, mb);
        bulk_g2s(dst + IN_PACKED_B,        sc + (size_t)local * SB_B,        SB_B,        mb);
        bulk_g2s(dst + IN_PACKED_B + SB_B, bi + (size_t)local * SB_B,        SB_B,        mb);
    };

    // Prologue: prefetch up to NSTAGES-1 tiles.
    if (tid == 0) {
        #pragma unroll
        for (int d = 0; d < NSTAGES - 1; ++d) {
            int t = (int)blockIdx.x + d * GRID;
            if (t < TOTAL_TILES) issue_loads(t, d);
        }
    }

    int ph[NSTAGES] = {0, 0, 0, 0};
    int it = 0;
    for (int t = blockIdx.x; t < TOTAL_TILES; t += GRID, ++it) {
        const int s = it & (NSTAGES - 1);

        // Prefetch tile t + (NSTAGES-1)*GRID into stage (s+NSTAGES-1)%NSTAGES.
        // That stage was last read at iteration it-1, which ended with
        // __syncthreads, so it is safe to overwrite.
        const int tn = t + (NSTAGES - 1) * GRID;
        if (tid == 0 && tn < TOTAL_TILES)
            issue_loads(tn, (s + NSTAGES - 1) & (NSTAGES - 1));

        mbar_wait(sbase + SMEM_MBAR + 16 * s, ph[s]);
        ph[s] ^= 1;

        // Dequantize smem -> registers -> direct coalesced STG.
        const char*  in   = smem + s * IN_STAGE_B;
        const int2*  pin  = (const int2*)in;
        const float* psc  = (const float*)(in + IN_PACKED_B);
        const float* pbi  = (const float*)(in + IN_PACKED_B + SB_B);

        int tensor = t >> 11;
        int local  = t & (TILES_PER_TENSOR - 1);
        float4* po = (float4*)(out
                     + (size_t)tensor * ((size_t)TILES_PER_TENSOR * OUT_TILE_B)
                     + (size_t)local * OUT_TILE_B);

        #pragma unroll
        for (int r = 0; r < TILE_ELEMS / 4 / NTHREADS; ++r) {    // 4 iters
            int idx = r * NTHREADS + tid;                         // float4 idx 0..1023
            int2  x  = pin[idx];
            int   b  = idx >> 3;                                  // 8 float4 per block
            float sc = psc[b];
            float bi = pbi[b];
            float4 v;
            v.x = (float)( x.x       & 15) * sc + bi;
            v.y = (float)((x.x >> 4) & 15) * sc + bi;
            v.z = (float)( x.y       & 15) * sc + bi;
            v.w = (float)((x.y >> 4) & 15) * sc + bi;
            po[idx] = v;
        }

        // All threads done reading stage s before it can be refilled next wrap.
        __syncthreads();
    }
}

extern "C" void kernel_launch(void* const* d_in, const int* in_sizes, int n_in,
                              void* d_out, int out_size)
{
    const char* kp = (const char*)d_in[0];
    const char* ks = (const char*)d_in[1];
    const char* kb = (const char*)d_in[2];
    const char* vp = (const char*)d_in[3];
    const char* vs = (const char*)d_in[4];
    const char* vb = (const char*)d_in[5];

    cudaFuncSetAttribute(kv_dequant_tma2,
                         cudaFuncAttributeMaxDynamicSharedMemorySize, SMEM_TOTAL);

    kv_dequant_tma2<<<GRID, NTHREADS, SMEM_TOTAL>>>(
        kp, ks, kb, vp, vs, vb, (char*)d_out);
}